// round 11
// baseline (speedup 1.0000x reference)
#include <cuda_runtime.h>
#include <cuda_bf16.h>

#define NPTS 8192
#define CDIM 64
#define HEADS 4
#define KNN 16
#define DH 16
#define FULLMASK 0xffffffffu

// ---------------- scratch (device globals; no allocations allowed) ----------------
__device__ float4 g_p4[NPTS];                       // x,y,z,|p|^2
__device__ float  g_xq[NPTS * CDIM];
__device__ float  g_xk[NPTS * CDIM];
__device__ float  g_xv[NPTS * CDIM];
__device__ int    g_idx[NPTS * KNN];

// ---------------- kernel 1: pack p + squared norm ----------------
__global__ void k_prep(const float* __restrict__ p) {
    int i = blockIdx.x * blockDim.x + threadIdx.x;
    if (i < NPTS) {
        float x = p[3 * i], y = p[3 * i + 1], z = p[3 * i + 2];
        float s = x * x;
        s += y * y;
        s += z * z;
        g_p4[i] = make_float4(x, y, z, s);
    }
}

// ---------------- kernel 2: xq = x@Wq, xk = x@Wk, xv = x@Wv ----------------
__global__ void __launch_bounds__(256) k_proj(const float* __restrict__ x,
                                              const float* __restrict__ Wq,
                                              const float* __restrict__ Wk,
                                              const float* __restrict__ Wv) {
    __shared__ float xs[64][65];
    int t = threadIdx.x;
    int row0 = blockIdx.x * 64;
    for (int i = t; i < 64 * 64; i += 256)
        xs[i >> 6][i & 63] = x[(row0 + (i >> 6)) * 64 + (i & 63)];
    __syncthreads();

    int c = t & 63;
    int rg = t >> 6;   // 0..3, rows rg*16 .. rg*16+15
    float aq[16], ak[16], av[16];
#pragma unroll
    for (int r = 0; r < 16; ++r) { aq[r] = 0.f; ak[r] = 0.f; av[r] = 0.f; }

    for (int k = 0; k < 64; ++k) {
        float wq = __ldg(&Wq[k * 64 + c]);
        float wk = __ldg(&Wk[k * 64 + c]);
        float wv = __ldg(&Wv[k * 64 + c]);
#pragma unroll
        for (int r = 0; r < 16; ++r) {
            float xv = xs[rg * 16 + r][k];
            aq[r] = fmaf(xv, wq, aq[r]);
            ak[r] = fmaf(xv, wk, ak[r]);
            av[r] = fmaf(xv, wv, av[r]);
        }
    }
#pragma unroll
    for (int r = 0; r < 16; ++r) {
        int row = row0 + rg * 16 + r;
        g_xq[row * 64 + c] = aq[r];
        g_xk[row * 64 + c] = ak[r];
        g_xv[row * 64 + c] = av[r];
    }
}

// ---------------- kernel 3: exact KNN top-16 via warp-distributed sorted list ----------------
__device__ __forceinline__ unsigned order_float(float f) {
    unsigned b = __float_as_uint(f);
    return (b & 0x80000000u) ? ~b : (b | 0x80000000u);
}

#define KNN_TILE 512

__global__ void __launch_bounds__(256) k_knn() {
    __shared__ float4 cbuf[KNN_TILE];                // 8 KB candidate tile
    int lane = threadIdx.x & 31;
    int w = threadIdx.x >> 5;
    int t = threadIdx.x;
    int gw = blockIdx.x * 8 + w;                     // query id

    float4 q = g_p4[gw];
    unsigned long long best = ~0ULL;                 // distributed sorted list
    float bestd2 = __int_as_float(0x7f800000);       // +inf
    unsigned long long tau = ~0ULL;
    float tau_d2 = __int_as_float(0x7f800000);

    for (int tile = 0; tile < NPTS; tile += KNN_TILE) {
        __syncthreads();
        cbuf[t]       = __ldg(&g_p4[tile + t]);
        cbuf[t + 256] = __ldg(&g_p4[tile + t + 256]);
        __syncthreads();

#pragma unroll 8
        for (int u = 0; u < KNN_TILE / 32; ++u) {
            int j = tile + u * 32 + lane;
            float4 cnd = cbuf[u * 32 + lane];
            float dot = q.x * cnd.x;
            dot = fmaf(q.y, cnd.y, dot);
            dot = fmaf(q.z, cnd.z, dot);
            float d2 = fmaf(-2.0f, dot, q.w + cnd.w);

            unsigned pend = __ballot_sync(FULLMASK, d2 <= tau_d2);
            if (pend) {
                unsigned long long key =
                    ((unsigned long long)order_float(d2) << 32) | (unsigned)j;
                pend &= __ballot_sync(FULLMASK, key < tau);
                while (pend) {
                    int src = __ffs(pend) - 1;
                    unsigned long long vb = __shfl_sync(FULLMASK, key, src);
                    float vd = __shfl_sync(FULLMASK, d2, src);
                    unsigned long long upk = __shfl_up_sync(FULLMASK, best, 1);
                    float upd = __shfl_up_sync(FULLMASK, bestd2, 1);
                    bool lt = vb < best;
                    unsigned m = __ballot_sync(FULLMASK, lt);
                    int fl = __ffs(m) - 1;
                    if (lt) {
                        best = (lane == fl) ? vb : upk;
                        bestd2 = (lane == fl) ? vd : upd;
                    }
                    tau = __shfl_sync(FULLMASK, best, 15);
                    tau_d2 = __shfl_sync(FULLMASK, bestd2, 15);
                    pend &= pend - 1;
                    pend &= __ballot_sync(FULLMASK, key < tau);
                }
            }
        }
    }

    if (lane < KNN)
        g_idx[gw * KNN + lane] = (int)(unsigned)(best & 0xffffffffu);
}

// ---------------- kernel 4 (fused): PPF + MLP-h + attention + Wo + LN + res + relu --------
// pe is never materialized:
//   score[h,k] = ( q.xk[j_k] + q.b2 + h_k . r[:,h] ) * 0.25,  r[c,h] = sum_d W2[c, h*16+d] q[h*16+d]
//   out[c]     = sum_k a[h,k] xv[j_k][c] + (sum_k a[h,k] h_k) @ W2[:,c] + b2[c]
__device__ __forceinline__ float angle_f(float ux, float uy, float uz,
                                         float vx, float vy, float vz) {
    float cx = uy * vz - uz * vy;
    float cy = uz * vx - ux * vz;
    float cz = ux * vy - uy * vx;
    float s = sqrtf(cx * cx + cy * cy + cz * cz + 1e-9f);
    float c = ux * vx + uy * vy + uz * vz;
    return atan2f(s, c);
}

__global__ void __launch_bounds__(256) k_fused(
    const float* __restrict__ p, const float* __restrict__ nrm,
    const float* __restrict__ x,
    const float* __restrict__ W1, const float* __restrict__ b1,
    const float* __restrict__ W2, const float* __restrict__ b2,
    const float* __restrict__ Wo,
    const float* __restrict__ lng, const float* __restrict__ lnb,
    float* __restrict__ out) {
    __shared__ float W1s[4][64];
    __shared__ float b1s[64], b2s[64];
    __shared__ float qs[4][64];
    __shared__ float ppfs[4][16][4];
    __shared__ float hbuf[4][16][69];   // stride 69: conflict-free row & col access
    __shared__ float rs[4][64][5];
    __shared__ float awb[4][4][17];
    __shared__ float gsm[4][4][68];
    __shared__ float obuf[4][64];
    __shared__ float redA[4][2], redB[4][2];
    __shared__ int   sidx[4][16];

    int tid = threadIdx.x;
    int pt = tid >> 6;
    int t = tid & 63;
    int n = blockIdx.x * 4 + pt;

    // block-wide constant loads
    W1s[tid >> 6][tid & 63] = W1[tid];          // 256 = 4*64
    if (tid < 64) b1s[tid] = b1[tid];
    else if (tid < 128) b2s[tid - 64] = b2[tid - 64];

    if (t < 16) sidx[pt][t] = g_idx[n * KNN + t];
    qs[pt][t] = g_xq[n * 64 + t];
    __syncthreads();

    // ---- stage A: PPF features (threads t<16, one neighbor each) ----
    if (t < 16) {
        int j = sidx[pt][t];
        float px = p[3 * n], py = p[3 * n + 1], pz = p[3 * n + 2];
        float dx = p[3 * j] - px, dy = p[3 * j + 1] - py, dz = p[3 * j + 2] - pz;
        float ncx = nrm[3 * n], ncy = nrm[3 * n + 1], ncz = nrm[3 * n + 2];
        float nrx = nrm[3 * j], nry = nrm[3 * j + 1], nrz = nrm[3 * j + 2];
        ppfs[pt][t][0] = angle_f(ncx, ncy, ncz, dx, dy, dz);
        ppfs[pt][t][1] = angle_f(nrx, nry, nrz, dx, dy, dz);
        ppfs[pt][t][2] = angle_f(ncx, ncy, ncz, nrx, nry, nrz);
        ppfs[pt][t][3] = sqrtf(dx * dx + dy * dy + dz * dz + 1e-9f);
    }
    __syncthreads();

    // ---- stage B: h = relu(ppf@W1+b1) (thread = channel), and r[c,h] ----
    {
        float w0 = W1s[0][t], w1v = W1s[1][t], w2v = W1s[2][t], w3 = W1s[3][t];
        float bb = b1s[t];
#pragma unroll
        for (int r = 0; r < 16; ++r) {
            float v = bb;
            v = fmaf(ppfs[pt][r][0], w0, v);
            v = fmaf(ppfs[pt][r][1], w1v, v);
            v = fmaf(ppfs[pt][r][2], w2v, v);
            v = fmaf(ppfs[pt][r][3], w3, v);
            hbuf[pt][r][t] = fmaxf(v, 0.f);
        }
        // r[c=t][h] = sum_{d in head h} W2[t][h*16+d] * q[h*16+d]
        const float4* wrow = (const float4*)&W2[t * 64];
#pragma unroll
        for (int hh = 0; hh < 4; ++hh) {
            float acc = 0.f;
#pragma unroll
            for (int d4 = 0; d4 < 4; ++d4) {
                float4 w4 = __ldg(&wrow[hh * 4 + d4]);
                int b = hh * 16 + d4 * 4;
                acc = fmaf(w4.x, qs[pt][b + 0], acc);
                acc = fmaf(w4.y, qs[pt][b + 1], acc);
                acc = fmaf(w4.z, qs[pt][b + 2], acc);
                acc = fmaf(w4.w, qs[pt][b + 3], acc);
            }
            rs[pt][t][hh] = acc;
        }
    }
    __syncthreads();

    // ---- stage C: scores + softmax (thread = (head hh, neighbor kk)) ----
    {
        int hh = t >> 4, kk = t & 15;
        int j = sidx[pt][kk];
        int base = hh * 16;
        float s = 0.f;
        const float4* krow = (const float4*)&g_xk[j * 64 + base];
#pragma unroll
        for (int d4 = 0; d4 < 4; ++d4) {
            float4 kv = __ldg(&krow[d4]);
            int b = base + d4 * 4;
            s = fmaf(qs[pt][b + 0], kv.x + b2s[b + 0], s);
            s = fmaf(qs[pt][b + 1], kv.y + b2s[b + 1], s);
            s = fmaf(qs[pt][b + 2], kv.z + b2s[b + 2], s);
            s = fmaf(qs[pt][b + 3], kv.w + b2s[b + 3], s);
        }
#pragma unroll
        for (int c = 0; c < 64; ++c)
            s = fmaf(hbuf[pt][kk][c], rs[pt][c][hh], s);
        s *= 0.25f;

        float mx = s;
#pragma unroll
        for (int off = 8; off; off >>= 1)
            mx = fmaxf(mx, __shfl_xor_sync(FULLMASK, mx, off));
        float e = expf(s - mx);
        float sum = e;
#pragma unroll
        for (int off = 8; off; off >>= 1)
            sum += __shfl_xor_sync(FULLMASK, sum, off);
        awb[pt][hh][kk] = e / sum;
    }
    __syncthreads();

    // ---- stage D: g[h][c] = sum_k a[h,k] h_k[c] (thread = channel) ----
    {
        float g0 = 0.f, g1 = 0.f, g2 = 0.f, g3 = 0.f;
#pragma unroll
        for (int kk = 0; kk < 16; ++kk) {
            float hk = hbuf[pt][kk][t];
            g0 = fmaf(awb[pt][0][kk], hk, g0);
            g1 = fmaf(awb[pt][1][kk], hk, g1);
            g2 = fmaf(awb[pt][2][kk], hk, g2);
            g3 = fmaf(awb[pt][3][kk], hk, g3);
        }
        gsm[pt][0][t] = g0; gsm[pt][1][t] = g1;
        gsm[pt][2][t] = g2; gsm[pt][3][t] = g3;
    }
    __syncthreads();

    // ---- stage E: out[c] = sum_k a*xv + g[h]@W2[:,c] + b2[c] ----
    {
        int hh = t >> 4;
        float acc = b2s[t];
#pragma unroll
        for (int c = 0; c < 64; ++c)
            acc = fmaf(gsm[pt][hh][c], __ldg(&W2[c * 64 + t]), acc);
#pragma unroll
        for (int kk = 0; kk < 16; ++kk)
            acc = fmaf(awb[pt][hh][kk], __ldg(&g_xv[sidx[pt][kk] * 64 + t]), acc);
        obuf[pt][t] = acc;
    }
    __syncthreads();

    // ---- tail: Wo, LayerNorm, residual, relu ----
    float y = 0.f;
#pragma unroll 8
    for (int c = 0; c < 64; ++c)
        y = fmaf(obuf[pt][c], __ldg(&Wo[c * 64 + t]), y);

    float s1 = y, s2 = y * y;
#pragma unroll
    for (int off = 16; off; off >>= 1) {
        s1 += __shfl_xor_sync(FULLMASK, s1, off);
        s2 += __shfl_xor_sync(FULLMASK, s2, off);
    }
    int wip = t >> 5;
    if ((t & 31) == 0) { redA[pt][wip] = s1; redB[pt][wip] = s2; }
    __syncthreads();
    float sum = redA[pt][0] + redA[pt][1];
    float sumsq = redB[pt][0] + redB[pt][1];
    float mu = sum * (1.f / 64.f);
    float var = fmaxf(sumsq * (1.f / 64.f) - mu * mu, 0.f);
    float yn = (y - mu) * rsqrtf(var + 1e-5f) * __ldg(&lng[t]) + __ldg(&lnb[t]);
    float res = yn + x[n * 64 + t];
    out[n * 64 + t] = fmaxf(res, 0.f);
}

// ---------------- launch ----------------
extern "C" void kernel_launch(void* const* d_in, const int* in_sizes, int n_in,
                              void* d_out, int out_size) {
    const float* p    = (const float*)d_in[0];
    const float* x    = (const float*)d_in[1];
    const float* nrm  = (const float*)d_in[2];
    const float* Wq   = (const float*)d_in[3];
    const float* Wk   = (const float*)d_in[4];
    const float* Wv   = (const float*)d_in[5];
    const float* Wo   = (const float*)d_in[6];
    const float* w1   = (const float*)d_in[7];
    const float* b1   = (const float*)d_in[8];
    const float* w2   = (const float*)d_in[9];
    const float* b2   = (const float*)d_in[10];
    const float* lng  = (const float*)d_in[11];
    const float* lnb  = (const float*)d_in[12];
    float* out = (float*)d_out;

    k_prep<<<NPTS / 256, 256>>>(p);
    k_proj<<<NPTS / 64, 256>>>(x, Wq, Wk, Wv);
    k_knn<<<NPTS / 8, 256>>>();
    k_fused<<<NPTS / 4, 256>>>(p, nrm, x, w1, b1, w2, b2, Wo, lng, lnb, out);
}